// round 2
// baseline (speedup 1.0000x reference)
#include <cuda_runtime.h>
#include <math.h>

#define BS   512
#define MM   8
#define TT   2048
#define NS   2047   // T-1 filter steps
#define DD   16
#define CH   8      // phase-2 chunk (steps staged in smem)

// Per-step affine-map matrices (shared across batches; ~4.7 MB total)
__device__ float g_M[NS * 256];   // M_t = F (I - K_t H)   [16][16]
__device__ float g_N[NS * 128];   // N_t = F K_t           [16][8]
__device__ float g_G[NS * 128];   // G_t = H M_t           [8][16]
__device__ float g_D[NS * 64];    // D_t = H N_t           [8][8]
__device__ int   g_tc;            // convergence step (steps >= g_tc are frozen copies)
__device__ unsigned char g_nan[BS];

// ---------------------------------------------------------------------------
// Kernel 0: per-batch NaN scan over x[:, :, 0..T-2]
// ---------------------------------------------------------------------------
__global__ void nan_scan_kernel(const float* __restrict__ x) {
    int b = blockIdx.x, tid = threadIdx.x;
    const float* xb = x + (size_t)b * MM * TT;
    int bad = 0;
    for (int idx = tid; idx < MM * TT; idx += 256) {
        int t = idx & (TT - 1);
        if (t < NS) {
            float v = xb[idx];
            bad |= isnan(v) ? 1 : 0;
        }
    }
    int any = __syncthreads_or(bad);
    if (tid == 0) g_nan[b] = any ? 1 : 0;
}

// ---------------------------------------------------------------------------
// Kernel 1: shared Riccati recursion -> M,N,G,D per step, with convergence exit
// Single block, 256 threads.
// ---------------------------------------------------------------------------
__global__ void phase1_kernel(const float* __restrict__ F_, const float* __restrict__ H_,
                              const float* __restrict__ Q_, const float* __restrict__ R_) {
    __shared__ float sF[256], sH[128], sQ[256], sR[64];
    __shared__ float cov[256], covn[256];
    __shared__ float P[128];        // cov H^T   [16][8]
    __shared__ float W[2][128];     // GJ workspace [8][16] (S | I)
    __shared__ float K[128];        // gain [16][8]
    __shared__ float CU[256];       // cov_u
    __shared__ float FC[256];       // F * sym(cov_u)
    __shared__ float Nn[128];       // F K
    __shared__ float Mm[256];       // F - (F K) H

    int tid = threadIdx.x;
    sF[tid] = F_[tid];
    sQ[tid] = Q_[tid];
    if (tid < 128) sH[tid] = H_[tid];
    if (tid < 64)  sR[tid] = R_[tid];
    cov[tid] = ((tid >> 4) == (tid & 15)) ? 1.f : 0.f;
    __syncthreads();

    int tc = NS;
    for (int t = 0; t < NS; t++) {
        // P = cov H^T
        if (tid < 128) {
            int i = tid >> 3, j = tid & 7;
            float s = 0.f;
            #pragma unroll
            for (int e = 0; e < 16; e++) s += cov[i * 16 + e] * sH[j * 16 + e];
            P[tid] = s;
        }
        __syncthreads();
        // W = [S | I],  S = H P + R
        if (tid < 128) {
            int a = tid >> 4, c = tid & 15;
            float v;
            if (c < 8) {
                float s = sR[a * 8 + c];
                #pragma unroll
                for (int e = 0; e < 16; e++) s += sH[a * 16 + e] * P[e * 8 + c];
                v = s;
            } else {
                v = (a == (c - 8)) ? 1.f : 0.f;
            }
            W[0][a * 16 + c] = v;
        }
        __syncthreads();
        // Gauss-Jordan (S is SPD -> no pivoting), ping-pong buffers
        #pragma unroll 1
        for (int k = 0; k < 8; k++) {
            int cur = k & 1;
            if (tid < 128) {
                int a = tid >> 4, c = tid & 15;
                float piv = W[cur][k * 16 + k];
                float wkc = W[cur][k * 16 + c] / piv;
                W[cur ^ 1][a * 16 + c] = (a == k) ? wkc
                                                  : W[cur][a * 16 + c] - W[cur][a * 16 + k] * wkc;
            }
            __syncthreads();
        }
        // K = P * Sinv  (Sinv = W[0][a][8+b])
        if (tid < 128) {
            int i = tid >> 3, j = tid & 7;
            float s = 0.f;
            #pragma unroll
            for (int a = 0; a < 8; a++) s += P[i * 8 + a] * W[0][a * 16 + 8 + j];
            K[tid] = s;
        }
        __syncthreads();
        // cov_u = cov - K P^T
        {
            int i = tid >> 4, j = tid & 15;
            float s = cov[tid];
            #pragma unroll
            for (int a = 0; a < 8; a++) s -= K[i * 8 + a] * P[j * 8 + a];
            CU[tid] = s;
        }
        __syncthreads();
        // FC = F * sym(cov_u);  N = F K
        {
            int i = tid >> 4, j = tid & 15;
            float s = 0.f;
            #pragma unroll
            for (int e = 0; e < 16; e++)
                s += sF[i * 16 + e] * 0.5f * (CU[e * 16 + j] + CU[j * 16 + e]);
            FC[tid] = s;
        }
        if (tid < 128) {
            int i = tid >> 3, a = tid & 7;
            float s = 0.f;
            #pragma unroll
            for (int e = 0; e < 16; e++) s += sF[i * 16 + e] * K[e * 8 + a];
            Nn[tid] = s;
        }
        __syncthreads();
        // covn = FC F^T + Q ;  M = F - N H
        {
            int i = tid >> 4, j = tid & 15;
            float s = sQ[tid];
            #pragma unroll
            for (int e = 0; e < 16; e++) s += FC[i * 16 + e] * sF[j * 16 + e];
            covn[tid] = s;
            float m = sF[tid];
            #pragma unroll
            for (int a = 0; a < 8; a++) m -= Nn[i * 8 + a] * sH[a * 16 + j];
            Mm[tid] = m;
        }
        __syncthreads();
        // G = H M ;  D = H N ;  store step matrices
        if (tid < 128) {
            int a = tid >> 4, j = tid & 15;
            float s = 0.f;
            #pragma unroll
            for (int e = 0; e < 16; e++) s += sH[a * 16 + e] * Mm[e * 16 + j];
            g_G[t * 128 + tid] = s;
        } else if (tid < 192) {
            int u = tid - 128, a = u >> 3, bcol = u & 7;
            float s = 0.f;
            #pragma unroll
            for (int e = 0; e < 16; e++) s += sH[a * 16 + e] * Nn[e * 8 + bcol];
            g_D[t * 64 + u] = s;
        }
        g_M[t * 256 + tid] = Mm[tid];
        if (tid < 128) g_N[t * 128 + tid] = Nn[tid];

        // convergence check (relative) and cov <- covn
        float dlt = fabsf(covn[tid] - cov[tid]);
        int big = dlt > 2e-5f * (fabsf(cov[tid]) + 1e-2f);
        int any = __syncthreads_or(big);
        cov[tid] = covn[tid];
        __syncthreads();
        if (!any) { tc = t + 1; break; }
    }
    if (tid == 0) g_tc = tc;
}

// ---------------------------------------------------------------------------
// Kernel 2: fill frozen tail [g_tc, NS) with step (g_tc - 1) matrices
// ---------------------------------------------------------------------------
__global__ void fill_kernel() {
    int t = blockIdx.x;
    int tc = g_tc;
    if (t < tc) return;
    int src = tc - 1;
    int tid = threadIdx.x;
    g_M[t * 256 + tid] = g_M[src * 256 + tid];
    if (tid < 128) {
        g_N[t * 128 + tid] = g_N[src * 128 + tid];
        g_G[t * 128 + tid] = g_G[src * 128 + tid];
    }
    if (tid < 64) g_D[t * 64 + tid] = g_D[src * 64 + tid];
}

// ---------------------------------------------------------------------------
// Kernel 3: per-batch mean recursion. 1 warp per batch, 8 warps per block
// sharing smem-staged chunks of M,N,G,D.
// Lanes 0..15: mean' = M mean + N obs
// Lanes 16..23: y     = G mean + D obs -> out
// Lanes 24..31: prefetch obs for t+1
// ---------------------------------------------------------------------------
__global__ void __launch_bounds__(256) phase2_kernel(const float* __restrict__ x,
                                                     float* __restrict__ out) {
    __shared__ __align__(16) float sM[CH][16][20];
    __shared__ __align__(16) float sN[CH][16][12];
    __shared__ __align__(16) float sG[CH][8][20];
    __shared__ __align__(16) float sD[CH][8][12];

    int tid = threadIdx.x;
    int w = tid >> 5, lane = tid & 31;
    int b = blockIdx.x * 8 + w;
    bool active = (g_nan[b] == 0);

    const float* xb = x + (size_t)b * MM * TT;
    float* ob = out + (size_t)b * MM * TT;

    float mean[16];
    #pragma unroll
    for (int i = 0; i < 16; i++) mean[i] = 0.f;
    if (active && lane < 8) ob[lane * TT + 0] = 0.f;

    float nextobs = 0.f;
    if (lane >= 24) nextobs = xb[(lane - 24) * TT + 0];
    float obs[8];

    int t = 0;
    for (int c0 = 0; c0 < NS; c0 += CH) {
        int nsteps = (NS - c0 < CH) ? (NS - c0) : CH;
        __syncthreads();
        // cooperative chunk load (coalesced LDG, padded STS)
        for (int idx = tid; idx < nsteps * 256; idx += 256) {
            int s = idx >> 8, r = (idx >> 4) & 15, cc = idx & 15;
            sM[s][r][cc] = g_M[(c0 + s) * 256 + (idx & 255)];
        }
        for (int idx = tid; idx < nsteps * 128; idx += 256) {
            int s = idx >> 7;
            int rn = (idx >> 3) & 15, cn = idx & 7;
            sN[s][rn][cn] = g_N[(c0 + s) * 128 + (idx & 127)];
            int rg = (idx >> 4) & 7, cg = idx & 15;
            sG[s][rg][cg] = g_G[(c0 + s) * 128 + (idx & 127)];
        }
        for (int idx = tid; idx < nsteps * 64; idx += 256) {
            int s = idx >> 6, r = (idx >> 3) & 7, cc = idx & 7;
            sD[s][r][cc] = g_D[(c0 + s) * 64 + (idx & 63)];
        }
        __syncthreads();

        if (active) {
            for (int s = 0; s < nsteps; s++, t++) {
                // broadcast obs_t from loader lanes
                #pragma unroll
                for (int j = 0; j < 8; j++)
                    obs[j] = __shfl_sync(0xffffffffu, nextobs, 24 + j);
                // prefetch obs_{t+1}
                if (lane >= 24 && (t + 1) < NS)
                    nextobs = xb[(lane - 24) * TT + (t + 1)];

                float nm = 0.f;
                if (lane < 16) {
                    const float4* Mr = (const float4*)&sM[s][lane][0];
                    float4 m0 = Mr[0], m1 = Mr[1], m2 = Mr[2], m3 = Mr[3];
                    const float4* Nr = (const float4*)&sN[s][lane][0];
                    float4 n0 = Nr[0], n1 = Nr[1];
                    float a0 = m0.x * mean[0] + m1.x * mean[4];
                    float a1 = m0.y * mean[1] + m1.y * mean[5];
                    float a2 = m0.z * mean[2] + m1.z * mean[6];
                    float a3 = m0.w * mean[3] + m1.w * mean[7];
                    a0 += m2.x * mean[8]  + m3.x * mean[12];
                    a1 += m2.y * mean[9]  + m3.y * mean[13];
                    a2 += m2.z * mean[10] + m3.z * mean[14];
                    a3 += m2.w * mean[11] + m3.w * mean[15];
                    a0 += n0.x * obs[0] + n1.x * obs[4];
                    a1 += n0.y * obs[1] + n1.y * obs[5];
                    a2 += n0.z * obs[2] + n1.z * obs[6];
                    a3 += n0.w * obs[3] + n1.w * obs[7];
                    nm = (a0 + a1) + (a2 + a3);
                } else if (lane < 24) {
                    int j = lane - 16;
                    const float4* Gr = (const float4*)&sG[s][j][0];
                    float4 g0 = Gr[0], g1 = Gr[1], g2 = Gr[2], g3 = Gr[3];
                    const float4* Dr = (const float4*)&sD[s][j][0];
                    float4 d0 = Dr[0], d1 = Dr[1];
                    float a0 = g0.x * mean[0] + g1.x * mean[4];
                    float a1 = g0.y * mean[1] + g1.y * mean[5];
                    float a2 = g0.z * mean[2] + g1.z * mean[6];
                    float a3 = g0.w * mean[3] + g1.w * mean[7];
                    a0 += g2.x * mean[8]  + g3.x * mean[12];
                    a1 += g2.y * mean[9]  + g3.y * mean[13];
                    a2 += g2.z * mean[10] + g3.z * mean[14];
                    a3 += g2.w * mean[11] + g3.w * mean[15];
                    a0 += d0.x * obs[0] + d1.x * obs[4];
                    a1 += d0.y * obs[1] + d1.y * obs[5];
                    a2 += d0.z * obs[2] + d1.z * obs[6];
                    a3 += d0.w * obs[3] + d1.w * obs[7];
                    ob[j * TT + t + 1] = (a0 + a1) + (a2 + a3);
                }
                // broadcast updated mean
                #pragma unroll
                for (int e = 0; e < 16; e++)
                    mean[e] = __shfl_sync(0xffffffffu, nm, e);
            }
        } else {
            t += nsteps;
        }
    }
}

// ---------------------------------------------------------------------------
// Kernel 4: fallback exact per-batch filter for NaN-containing batches
// (never runs for normal-distributed inputs; launched every call for
//  deterministic, capturable behavior)
// ---------------------------------------------------------------------------
__global__ void slow_kernel(const float* __restrict__ x, const float* __restrict__ F_,
                            const float* __restrict__ H_, const float* __restrict__ Q_,
                            const float* __restrict__ R_, float* __restrict__ out) {
    int b = blockIdx.x;
    if (!g_nan[b]) return;
    int tid = threadIdx.x;
    __shared__ float sF[256], sH[128], sQ[256], sR[64];
    __shared__ float cov[256], covn[256], P[128], W[2][128], K[128], CU[256], FC[256];
    __shared__ float mean[16], meanu[16], meanp[16], obs[8], resid[8];
    __shared__ int nanb;

    sF[tid] = F_[tid];
    sQ[tid] = Q_[tid];
    if (tid < 128) sH[tid] = H_[tid];
    if (tid < 64)  sR[tid] = R_[tid];
    cov[tid] = ((tid >> 4) == (tid & 15)) ? 1.f : 0.f;
    if (tid < 16) mean[tid] = 0.f;
    if (tid < 8)  out[((size_t)b * MM + tid) * TT] = 0.f;
    __syncthreads();

    for (int t = 0; t < NS; t++) {
        if (tid == 0) {
            int nb = 0;
            for (int j = 0; j < 8; j++) {
                float v = x[((size_t)b * MM + j) * TT + t];
                if (isnan(v)) { nb = 1; v = 0.f; }
                obs[j] = v;
            }
            nanb = nb;
        }
        __syncthreads();
        if (tid < 128) {
            int i = tid >> 3, j = tid & 7;
            float s = 0.f;
            #pragma unroll
            for (int e = 0; e < 16; e++) s += cov[i * 16 + e] * sH[j * 16 + e];
            P[tid] = s;
        }
        if (tid >= 128 && tid < 136) {
            int j = tid - 128;
            float s = obs[j];
            #pragma unroll
            for (int e = 0; e < 16; e++) s -= sH[j * 16 + e] * mean[e];
            resid[j] = s;
        }
        __syncthreads();
        if (tid < 128) {
            int a = tid >> 4, c = tid & 15;
            float v;
            if (c < 8) {
                float s = sR[a * 8 + c];
                #pragma unroll
                for (int e = 0; e < 16; e++) s += sH[a * 16 + e] * P[e * 8 + c];
                v = s;
            } else v = (a == (c - 8)) ? 1.f : 0.f;
            W[0][a * 16 + c] = v;
        }
        __syncthreads();
        #pragma unroll 1
        for (int k = 0; k < 8; k++) {
            int cur = k & 1;
            if (tid < 128) {
                int a = tid >> 4, c = tid & 15;
                float piv = W[cur][k * 16 + k];
                float wkc = W[cur][k * 16 + c] / piv;
                W[cur ^ 1][a * 16 + c] = (a == k) ? wkc
                                                  : W[cur][a * 16 + c] - W[cur][a * 16 + k] * wkc;
            }
            __syncthreads();
        }
        if (tid < 128) {
            int i = tid >> 3, j = tid & 7;
            float s = 0.f;
            #pragma unroll
            for (int a = 0; a < 8; a++) s += P[i * 8 + a] * W[0][a * 16 + 8 + j];
            K[tid] = s;
        }
        __syncthreads();
        if (tid < 16) {
            float s = mean[tid];
            #pragma unroll
            for (int a = 0; a < 8; a++) s += K[tid * 8 + a] * resid[a];
            meanu[tid] = nanb ? mean[tid] : s;
        }
        {
            int i = tid >> 4, j = tid & 15;
            float s = cov[tid];
            #pragma unroll
            for (int a = 0; a < 8; a++) s -= K[i * 8 + a] * P[j * 8 + a];
            CU[tid] = nanb ? cov[tid] : s;
        }
        __syncthreads();
        {
            int i = tid >> 4, j = tid & 15;
            float s = 0.f;
            #pragma unroll
            for (int e = 0; e < 16; e++)
                s += sF[i * 16 + e] * 0.5f * (CU[e * 16 + j] + CU[j * 16 + e]);
            FC[tid] = s;
        }
        if (tid < 16) {
            float s = 0.f;
            #pragma unroll
            for (int e = 0; e < 16; e++) s += sF[tid * 16 + e] * meanu[e];
            meanp[tid] = s;
        }
        __syncthreads();
        {
            int i = tid >> 4, j = tid & 15;
            float s = sQ[tid];
            #pragma unroll
            for (int e = 0; e < 16; e++) s += FC[i * 16 + e] * sF[j * 16 + e];
            covn[tid] = s;
        }
        if (tid < 8) {
            float s = 0.f;
            #pragma unroll
            for (int e = 0; e < 16; e++) s += sH[tid * 16 + e] * meanp[e];
            out[((size_t)b * MM + tid) * TT + t + 1] = s;
        }
        __syncthreads();
        cov[tid] = covn[tid];
        if (tid < 16) mean[tid] = meanp[tid];
        __syncthreads();
    }
}

// ---------------------------------------------------------------------------
extern "C" void kernel_launch(void* const* d_in, const int* in_sizes, int n_in,
                              void* d_out, int out_size) {
    const float* x = (const float*)d_in[0];
    const float* F = (const float*)d_in[1];
    const float* H = (const float*)d_in[2];
    const float* Q = (const float*)d_in[3];
    const float* R = (const float*)d_in[4];
    float* out = (float*)d_out;

    nan_scan_kernel<<<BS, 256>>>(x);
    phase1_kernel<<<1, 256>>>(F, H, Q, R);
    fill_kernel<<<NS, 256>>>();
    phase2_kernel<<<64, 256>>>(x, out);
    slow_kernel<<<BS, 256>>>(x, F, H, Q, R, out);
}

// round 3
// speedup vs baseline: 1.0183x; 1.0183x over previous
#include <cuda_runtime.h>
#include <math.h>

#define BS   512
#define MM   8
#define TT   2048
#define NS   2047   // T-1 filter steps
#define DD   16
#define CH   8      // phase-2 chunk (steps staged in smem)

// Per-step affine-map matrices (shared across batches; ~4.7 MB total)
__device__ float g_M[NS * 256];   // M_t = F (I - K_t H)   [16][16]
__device__ float g_N[NS * 128];   // N_t = F K_t           [16][8]
__device__ float g_G[NS * 128];   // G_t = H M_t           [8][16]
__device__ float g_D[NS * 64];    // D_t = H N_t           [8][8]
__device__ int   g_tc;            // convergence step (steps >= g_tc are frozen copies)
__device__ unsigned char g_nan[BS];

// ---------------------------------------------------------------------------
// Kernel 0: per-batch NaN scan over x[:, :, 0..T-2]
// ---------------------------------------------------------------------------
__global__ void nan_scan_kernel(const float* __restrict__ x) {
    int b = blockIdx.x, tid = threadIdx.x;
    const float* xb = x + (size_t)b * MM * TT;
    int bad = 0;
    for (int idx = tid; idx < MM * TT; idx += 256) {
        int t = idx & (TT - 1);
        if (t < NS) {
            float v = xb[idx];
            bad |= isnan(v) ? 1 : 0;
        }
    }
    int any = __syncthreads_or(bad);
    if (tid == 0) g_nan[b] = any ? 1 : 0;
}

// ---------------------------------------------------------------------------
// Kernel 1: shared Riccati recursion -> M,N,G,D per step, with convergence exit
// Single block, 256 threads.
// ---------------------------------------------------------------------------
__global__ void phase1_kernel(const float* __restrict__ F_, const float* __restrict__ H_,
                              const float* __restrict__ Q_, const float* __restrict__ R_) {
    __shared__ float sF[256], sH[128], sQ[256], sR[64];
    __shared__ float cov[256], covn[256];
    __shared__ float P[128];        // cov H^T   [16][8]
    __shared__ float W[2][128];     // GJ workspace [8][16] (S | I)
    __shared__ float K[128];        // gain [16][8]
    __shared__ float CU[256];       // cov_u
    __shared__ float FC[256];       // F * sym(cov_u)
    __shared__ float Nn[128];       // F K
    __shared__ float Mm[256];       // F - (F K) H

    int tid = threadIdx.x;
    sF[tid] = F_[tid];
    sQ[tid] = Q_[tid];
    if (tid < 128) sH[tid] = H_[tid];
    if (tid < 64)  sR[tid] = R_[tid];
    cov[tid] = ((tid >> 4) == (tid & 15)) ? 1.f : 0.f;
    __syncthreads();

    int tc = NS;
    for (int t = 0; t < NS; t++) {
        // P = cov H^T
        if (tid < 128) {
            int i = tid >> 3, j = tid & 7;
            float s = 0.f;
            #pragma unroll
            for (int e = 0; e < 16; e++) s += cov[i * 16 + e] * sH[j * 16 + e];
            P[tid] = s;
        }
        __syncthreads();
        // W = [S | I],  S = H P + R
        if (tid < 128) {
            int a = tid >> 4, c = tid & 15;
            float v;
            if (c < 8) {
                float s = sR[a * 8 + c];
                #pragma unroll
                for (int e = 0; e < 16; e++) s += sH[a * 16 + e] * P[e * 8 + c];
                v = s;
            } else {
                v = (a == (c - 8)) ? 1.f : 0.f;
            }
            W[0][a * 16 + c] = v;
        }
        __syncthreads();
        // Gauss-Jordan (S is SPD -> no pivoting), ping-pong buffers
        #pragma unroll 1
        for (int k = 0; k < 8; k++) {
            int cur = k & 1;
            if (tid < 128) {
                int a = tid >> 4, c = tid & 15;
                float piv = W[cur][k * 16 + k];
                float wkc = W[cur][k * 16 + c] / piv;
                W[cur ^ 1][a * 16 + c] = (a == k) ? wkc
                                                  : W[cur][a * 16 + c] - W[cur][a * 16 + k] * wkc;
            }
            __syncthreads();
        }
        // K = P * Sinv  (Sinv = W[0][a][8+b])
        if (tid < 128) {
            int i = tid >> 3, j = tid & 7;
            float s = 0.f;
            #pragma unroll
            for (int a = 0; a < 8; a++) s += P[i * 8 + a] * W[0][a * 16 + 8 + j];
            K[tid] = s;
        }
        __syncthreads();
        // cov_u = cov - K P^T
        {
            int i = tid >> 4, j = tid & 15;
            float s = cov[tid];
            #pragma unroll
            for (int a = 0; a < 8; a++) s -= K[i * 8 + a] * P[j * 8 + a];
            CU[tid] = s;
        }
        __syncthreads();
        // FC = F * sym(cov_u);  N = F K
        {
            int i = tid >> 4, j = tid & 15;
            float s = 0.f;
            #pragma unroll
            for (int e = 0; e < 16; e++)
                s += sF[i * 16 + e] * 0.5f * (CU[e * 16 + j] + CU[j * 16 + e]);
            FC[tid] = s;
        }
        if (tid < 128) {
            int i = tid >> 3, a = tid & 7;
            float s = 0.f;
            #pragma unroll
            for (int e = 0; e < 16; e++) s += sF[i * 16 + e] * K[e * 8 + a];
            Nn[tid] = s;
        }
        __syncthreads();
        // covn = FC F^T + Q ;  M = F - N H
        {
            int i = tid >> 4, j = tid & 15;
            float s = sQ[tid];
            #pragma unroll
            for (int e = 0; e < 16; e++) s += FC[i * 16 + e] * sF[j * 16 + e];
            covn[tid] = s;
            float m = sF[tid];
            #pragma unroll
            for (int a = 0; a < 8; a++) m -= Nn[i * 8 + a] * sH[a * 16 + j];
            Mm[tid] = m;
        }
        __syncthreads();
        // G = H M ;  D = H N ;  store step matrices
        if (tid < 128) {
            int a = tid >> 4, j = tid & 15;
            float s = 0.f;
            #pragma unroll
            for (int e = 0; e < 16; e++) s += sH[a * 16 + e] * Mm[e * 16 + j];
            g_G[t * 128 + tid] = s;
        } else if (tid < 192) {
            int u = tid - 128, a = u >> 3, bcol = u & 7;
            float s = 0.f;
            #pragma unroll
            for (int e = 0; e < 16; e++) s += sH[a * 16 + e] * Nn[e * 8 + bcol];
            g_D[t * 64 + u] = s;
        }
        g_M[t * 256 + tid] = Mm[tid];
        if (tid < 128) g_N[t * 128 + tid] = Nn[tid];

        // convergence check (relative) and cov <- covn
        float dlt = fabsf(covn[tid] - cov[tid]);
        int big = dlt > 2e-5f * (fabsf(cov[tid]) + 1e-2f);
        int any = __syncthreads_or(big);
        cov[tid] = covn[tid];
        __syncthreads();
        if (!any) { tc = t + 1; break; }
    }
    if (tid == 0) g_tc = tc;
}

// ---------------------------------------------------------------------------
// Kernel 2: fill frozen tail [g_tc, NS) with step (g_tc - 1) matrices
// ---------------------------------------------------------------------------
__global__ void fill_kernel() {
    int t = blockIdx.x;
    int tc = g_tc;
    if (t < tc) return;
    int src = tc - 1;
    int tid = threadIdx.x;
    g_M[t * 256 + tid] = g_M[src * 256 + tid];
    if (tid < 128) {
        g_N[t * 128 + tid] = g_N[src * 128 + tid];
        g_G[t * 128 + tid] = g_G[src * 128 + tid];
    }
    if (tid < 64) g_D[t * 64 + tid] = g_D[src * 64 + tid];
}

// ---------------------------------------------------------------------------
// Kernel 3: per-batch mean recursion. 1 warp per batch, 8 warps per block
// sharing smem-staged chunks of M,N,G,D.
// Lanes 0..15: mean' = M mean + N obs
// Lanes 16..23: y     = G mean + D obs -> out
// Lanes 24..31: prefetch obs for t+1
// ---------------------------------------------------------------------------
__global__ void __launch_bounds__(256) phase2_kernel(const float* __restrict__ x,
                                                     float* __restrict__ out) {
    __shared__ __align__(16) float sM[CH][16][20];
    __shared__ __align__(16) float sN[CH][16][12];
    __shared__ __align__(16) float sG[CH][8][20];
    __shared__ __align__(16) float sD[CH][8][12];

    int tid = threadIdx.x;
    int w = tid >> 5, lane = tid & 31;
    int b = blockIdx.x * 8 + w;
    bool active = (g_nan[b] == 0);

    const float* xb = x + (size_t)b * MM * TT;
    float* ob = out + (size_t)b * MM * TT;

    float mean[16];
    #pragma unroll
    for (int i = 0; i < 16; i++) mean[i] = 0.f;
    if (active && lane < 8) ob[lane * TT + 0] = 0.f;

    float nextobs = 0.f;
    if (lane >= 24) nextobs = xb[(lane - 24) * TT + 0];
    float obs[8];

    int t = 0;
    for (int c0 = 0; c0 < NS; c0 += CH) {
        int nsteps = (NS - c0 < CH) ? (NS - c0) : CH;
        __syncthreads();
        // cooperative chunk load (coalesced LDG, padded STS)
        for (int idx = tid; idx < nsteps * 256; idx += 256) {
            int s = idx >> 8, r = (idx >> 4) & 15, cc = idx & 15;
            sM[s][r][cc] = g_M[(c0 + s) * 256 + (idx & 255)];
        }
        for (int idx = tid; idx < nsteps * 128; idx += 256) {
            int s = idx >> 7;
            int rn = (idx >> 3) & 15, cn = idx & 7;
            sN[s][rn][cn] = g_N[(c0 + s) * 128 + (idx & 127)];
            int rg = (idx >> 4) & 7, cg = idx & 15;
            sG[s][rg][cg] = g_G[(c0 + s) * 128 + (idx & 127)];
        }
        for (int idx = tid; idx < nsteps * 64; idx += 256) {
            int s = idx >> 6, r = (idx >> 3) & 7, cc = idx & 7;
            sD[s][r][cc] = g_D[(c0 + s) * 64 + (idx & 63)];
        }
        __syncthreads();

        if (active) {
            for (int s = 0; s < nsteps; s++, t++) {
                // broadcast obs_t from loader lanes
                #pragma unroll
                for (int j = 0; j < 8; j++)
                    obs[j] = __shfl_sync(0xffffffffu, nextobs, 24 + j);
                // prefetch obs_{t+1}
                if (lane >= 24 && (t + 1) < NS)
                    nextobs = xb[(lane - 24) * TT + (t + 1)];

                float nm = 0.f;
                if (lane < 16) {
                    const float4* Mr = (const float4*)&sM[s][lane][0];
                    float4 m0 = Mr[0], m1 = Mr[1], m2 = Mr[2], m3 = Mr[3];
                    const float4* Nr = (const float4*)&sN[s][lane][0];
                    float4 n0 = Nr[0], n1 = Nr[1];
                    float a0 = m0.x * mean[0] + m1.x * mean[4];
                    float a1 = m0.y * mean[1] + m1.y * mean[5];
                    float a2 = m0.z * mean[2] + m1.z * mean[6];
                    float a3 = m0.w * mean[3] + m1.w * mean[7];
                    a0 += m2.x * mean[8]  + m3.x * mean[12];
                    a1 += m2.y * mean[9]  + m3.y * mean[13];
                    a2 += m2.z * mean[10] + m3.z * mean[14];
                    a3 += m2.w * mean[11] + m3.w * mean[15];
                    a0 += n0.x * obs[0] + n1.x * obs[4];
                    a1 += n0.y * obs[1] + n1.y * obs[5];
                    a2 += n0.z * obs[2] + n1.z * obs[6];
                    a3 += n0.w * obs[3] + n1.w * obs[7];
                    nm = (a0 + a1) + (a2 + a3);
                } else if (lane < 24) {
                    int j = lane - 16;
                    const float4* Gr = (const float4*)&sG[s][j][0];
                    float4 g0 = Gr[0], g1 = Gr[1], g2 = Gr[2], g3 = Gr[3];
                    const float4* Dr = (const float4*)&sD[s][j][0];
                    float4 d0 = Dr[0], d1 = Dr[1];
                    float a0 = g0.x * mean[0] + g1.x * mean[4];
                    float a1 = g0.y * mean[1] + g1.y * mean[5];
                    float a2 = g0.z * mean[2] + g1.z * mean[6];
                    float a3 = g0.w * mean[3] + g1.w * mean[7];
                    a0 += g2.x * mean[8]  + g3.x * mean[12];
                    a1 += g2.y * mean[9]  + g3.y * mean[13];
                    a2 += g2.z * mean[10] + g3.z * mean[14];
                    a3 += g2.w * mean[11] + g3.w * mean[15];
                    a0 += d0.x * obs[0] + d1.x * obs[4];
                    a1 += d0.y * obs[1] + d1.y * obs[5];
                    a2 += d0.z * obs[2] + d1.z * obs[6];
                    a3 += d0.w * obs[3] + d1.w * obs[7];
                    ob[j * TT + t + 1] = (a0 + a1) + (a2 + a3);
                }
                // broadcast updated mean
                #pragma unroll
                for (int e = 0; e < 16; e++)
                    mean[e] = __shfl_sync(0xffffffffu, nm, e);
            }
        } else {
            t += nsteps;
        }
    }
}

// ---------------------------------------------------------------------------
// Kernel 4: fallback exact per-batch filter for NaN-containing batches
// (never runs for normal-distributed inputs; launched every call for
//  deterministic, capturable behavior)
// ---------------------------------------------------------------------------
__global__ void slow_kernel(const float* __restrict__ x, const float* __restrict__ F_,
                            const float* __restrict__ H_, const float* __restrict__ Q_,
                            const float* __restrict__ R_, float* __restrict__ out) {
    int b = blockIdx.x;
    if (!g_nan[b]) return;
    int tid = threadIdx.x;
    __shared__ float sF[256], sH[128], sQ[256], sR[64];
    __shared__ float cov[256], covn[256], P[128], W[2][128], K[128], CU[256], FC[256];
    __shared__ float mean[16], meanu[16], meanp[16], obs[8], resid[8];
    __shared__ int nanb;

    sF[tid] = F_[tid];
    sQ[tid] = Q_[tid];
    if (tid < 128) sH[tid] = H_[tid];
    if (tid < 64)  sR[tid] = R_[tid];
    cov[tid] = ((tid >> 4) == (tid & 15)) ? 1.f : 0.f;
    if (tid < 16) mean[tid] = 0.f;
    if (tid < 8)  out[((size_t)b * MM + tid) * TT] = 0.f;
    __syncthreads();

    for (int t = 0; t < NS; t++) {
        if (tid == 0) {
            int nb = 0;
            for (int j = 0; j < 8; j++) {
                float v = x[((size_t)b * MM + j) * TT + t];
                if (isnan(v)) { nb = 1; v = 0.f; }
                obs[j] = v;
            }
            nanb = nb;
        }
        __syncthreads();
        if (tid < 128) {
            int i = tid >> 3, j = tid & 7;
            float s = 0.f;
            #pragma unroll
            for (int e = 0; e < 16; e++) s += cov[i * 16 + e] * sH[j * 16 + e];
            P[tid] = s;
        }
        if (tid >= 128 && tid < 136) {
            int j = tid - 128;
            float s = obs[j];
            #pragma unroll
            for (int e = 0; e < 16; e++) s -= sH[j * 16 + e] * mean[e];
            resid[j] = s;
        }
        __syncthreads();
        if (tid < 128) {
            int a = tid >> 4, c = tid & 15;
            float v;
            if (c < 8) {
                float s = sR[a * 8 + c];
                #pragma unroll
                for (int e = 0; e < 16; e++) s += sH[a * 16 + e] * P[e * 8 + c];
                v = s;
            } else v = (a == (c - 8)) ? 1.f : 0.f;
            W[0][a * 16 + c] = v;
        }
        __syncthreads();
        #pragma unroll 1
        for (int k = 0; k < 8; k++) {
            int cur = k & 1;
            if (tid < 128) {
                int a = tid >> 4, c = tid & 15;
                float piv = W[cur][k * 16 + k];
                float wkc = W[cur][k * 16 + c] / piv;
                W[cur ^ 1][a * 16 + c] = (a == k) ? wkc
                                                  : W[cur][a * 16 + c] - W[cur][a * 16 + k] * wkc;
            }
            __syncthreads();
        }
        if (tid < 128) {
            int i = tid >> 3, j = tid & 7;
            float s = 0.f;
            #pragma unroll
            for (int a = 0; a < 8; a++) s += P[i * 8 + a] * W[0][a * 16 + 8 + j];
            K[tid] = s;
        }
        __syncthreads();
        if (tid < 16) {
            float s = mean[tid];
            #pragma unroll
            for (int a = 0; a < 8; a++) s += K[tid * 8 + a] * resid[a];
            meanu[tid] = nanb ? mean[tid] : s;
        }
        {
            int i = tid >> 4, j = tid & 15;
            float s = cov[tid];
            #pragma unroll
            for (int a = 0; a < 8; a++) s -= K[i * 8 + a] * P[j * 8 + a];
            CU[tid] = nanb ? cov[tid] : s;
        }
        __syncthreads();
        {
            int i = tid >> 4, j = tid & 15;
            float s = 0.f;
            #pragma unroll
            for (int e = 0; e < 16; e++)
                s += sF[i * 16 + e] * 0.5f * (CU[e * 16 + j] + CU[j * 16 + e]);
            FC[tid] = s;
        }
        if (tid < 16) {
            float s = 0.f;
            #pragma unroll
            for (int e = 0; e < 16; e++) s += sF[tid * 16 + e] * meanu[e];
            meanp[tid] = s;
        }
        __syncthreads();
        {
            int i = tid >> 4, j = tid & 15;
            float s = sQ[tid];
            #pragma unroll
            for (int e = 0; e < 16; e++) s += FC[i * 16 + e] * sF[j * 16 + e];
            covn[tid] = s;
        }
        if (tid < 8) {
            float s = 0.f;
            #pragma unroll
            for (int e = 0; e < 16; e++) s += sH[tid * 16 + e] * meanp[e];
            out[((size_t)b * MM + tid) * TT + t + 1] = s;
        }
        __syncthreads();
        cov[tid] = covn[tid];
        if (tid < 16) mean[tid] = meanp[tid];
        __syncthreads();
    }
}

// ---------------------------------------------------------------------------
extern "C" void kernel_launch(void* const* d_in, const int* in_sizes, int n_in,
                              void* d_out, int out_size) {
    const float* x = (const float*)d_in[0];
    const float* F = (const float*)d_in[1];
    const float* H = (const float*)d_in[2];
    const float* Q = (const float*)d_in[3];
    const float* R = (const float*)d_in[4];
    float* out = (float*)d_out;

    nan_scan_kernel<<<BS, 256>>>(x);
    phase1_kernel<<<1, 256>>>(F, H, Q, R);
    fill_kernel<<<NS, 256>>>();
    phase2_kernel<<<64, 256>>>(x, out);
    slow_kernel<<<BS, 256>>>(x, F, H, Q, R, out);
}